// round 15
// baseline (speedup 1.0000x reference)
#include <cuda_runtime.h>
#include <cuda_fp16.h>
#include <math.h>
#include <stdint.h>

// Problem constants (fixed by the reference)
#define B_   16
#define NQ_  2048
#define NK_  2048
#define D_   128

#define BN   64      // keys per tile
#define NT   32      // NK_/BN
#define NTHREADS 256 // 8 warps

// smem pitches in halves — word-pitch ≡ 4 (mod 32) -> conflict-free ldmatrix
#define QPH 136
#define KPH 136
#define VPH 136

// ---- lsum kernel (BM=128) smem layout ----
#define BML      128
#define LQS_OFF   0
#define LQS_BYTES (BML * QPH * 2)               // 34816
#define LKS_OFF   (LQS_OFF + LQS_BYTES)
#define LKS_BYTES (BN * KPH * 2)                // 17408 per buffer
#define LSM_BYTES (LKS_OFF + 2 * LKS_BYTES)     // 69632

// ---- attn kernel (BM=64) smem layout ----
#define BMA      64
#define AQS_OFF   0
#define AQS_BYTES (BMA * QPH * 2)               // 17408
#define AKS_OFF   (AQS_OFF + AQS_BYTES)
#define AKS_BYTES (BN * KPH * 2)                // 17408 per buffer
#define AVS_OFF   (AKS_OFF + 2 * AKS_BYTES)
#define AVS_BYTES (BN * VPH * 2)                // 17408 per buffer
#define ASM_BYTES (AVS_OFF + 2 * AVS_BYTES)     // 87040  (x2 CTAs = 174080)
#define RP  132                                  // O-reduction pitch (floats)

__device__ float  g_gate[NK_];                     // gate * scale * log2(e)
__device__ float  g_inv_l[B_ * NQ_];
__device__ __half g_Kh[(size_t)B_ * NK_ * D_];     // K * gate * scale * log2e
__device__ __half g_Vh[(size_t)B_ * NK_ * D_];     // V fp16 [key][d]

// ---------------------------------------------------------------------------
__global__ void gate_kernel(const float* __restrict__ phases) {
    int k = blockIdx.x * blockDim.x + threadIdx.x;
    if (k < NK_) {
        const float TWO_PI = 6.283185307179586f;
        const float INV_2PW2 = 1.0f / 1.2337005501361697f; // 2*(2pi/8)^2
        const float SCALE = 0.08838834764831845f;          // 1/sqrt(128)
        const float LOG2E = 1.4426950408889634f;
        float p = fabsf(phases[k]);
        float pd = fminf(p, TWO_PI - p);
        g_gate[k] = expf(-pd * pd * INV_2PW2) * SCALE * LOG2E;
    }
}

__global__ void convK_kernel(const float* __restrict__ K) {
    int i = blockIdx.x * blockDim.x + threadIdx.x;   // < B*NK*D/4 = 2^20
    int d4  = (i & 31) << 2;
    int row = i >> 5;
    float gs = g_gate[row & (NK_ - 1)];
    float4 v = *(const float4*)(K + (size_t)row * D_ + d4);
    __half2 h0 = __floats2half2_rn(v.x * gs, v.y * gs);
    __half2 h1 = __floats2half2_rn(v.z * gs, v.w * gs);
    uint2 u = make_uint2(*(uint32_t*)&h0, *(uint32_t*)&h1);
    *(uint2*)&g_Kh[(size_t)row * D_ + d4] = u;
}

__global__ void convV_kernel(const float* __restrict__ V) {
    int i = blockIdx.x * blockDim.x + threadIdx.x;   // < 2^20
    int d4  = (i & 31) << 2;
    int row = i >> 5;
    float4 v = *(const float4*)(V + (size_t)row * D_ + d4);
    __half2 h0 = __floats2half2_rn(v.x, v.y);
    __half2 h1 = __floats2half2_rn(v.z, v.w);
    uint2 u = make_uint2(*(uint32_t*)&h0, *(uint32_t*)&h1);
    *(uint2*)&g_Vh[(size_t)row * D_ + d4] = u;
}

// ---------------------------------------------------------------------------
__device__ __forceinline__ void mma_f16(
    float& d0, float& d1, float& d2, float& d3,
    uint32_t a0, uint32_t a1, uint32_t a2, uint32_t a3,
    uint32_t b0, uint32_t b1)
{
    asm volatile(
        "mma.sync.aligned.m16n8k16.row.col.f32.f16.f16.f32 "
        "{%0,%1,%2,%3}, {%4,%5,%6,%7}, {%8,%9}, {%0,%1,%2,%3};"
        : "+f"(d0), "+f"(d1), "+f"(d2), "+f"(d3)
        : "r"(a0), "r"(a1), "r"(a2), "r"(a3), "r"(b0), "r"(b1));
}

__device__ __forceinline__ void ldsm_x4(uint32_t* r, uint32_t addr) {
    asm volatile("ldmatrix.sync.aligned.m8n8.x4.shared.b16 {%0,%1,%2,%3}, [%4];"
                 : "=r"(r[0]), "=r"(r[1]), "=r"(r[2]), "=r"(r[3]) : "r"(addr));
}

__device__ __forceinline__ void ldsm_x4_trans(uint32_t* r, uint32_t addr) {
    asm volatile("ldmatrix.sync.aligned.m8n8.x4.trans.shared.b16 {%0,%1,%2,%3}, [%4];"
                 : "=r"(r[0]), "=r"(r[1]), "=r"(r[2]), "=r"(r[3]) : "r"(addr));
}

__device__ __forceinline__ void cp16(uint32_t dst, const void* src) {
    asm volatile("cp.async.ca.shared.global [%0], [%1], 16;"
                 :: "r"(dst), "l"(src));
}

// ---------------------------------------------------------------------------
// Pass 1: l[b,q] = sum_k exp2(q . k'), k' = K*gate*scale*log2e. Writes inv_l.
// 8 warps, warp = m16 slab, full n64 per tile. Q fragments hoisted in regs.
// ---------------------------------------------------------------------------
extern __shared__ char smem[];

__global__ void __launch_bounds__(NTHREADS, 2)
lsum_kernel(const float* __restrict__ Q)
{
    uint32_t sb = (uint32_t)__cvta_generic_to_shared(smem);
    uint32_t* Qsw = (uint32_t*)(smem + LQS_OFF);

    const int b    = blockIdx.y;
    const int brow = b * NQ_ + blockIdx.x * BML;

    const int tid  = threadIdx.x;
    const int lane = tid & 31;
    const int wm   = tid >> 5;         // 0..7 -> m16 slab
    const int g    = lane >> 2;
    const int t    = lane & 3;
    const int mi   = lane >> 3;
    const int rr   = lane & 7;

    const float* Qg = Q + (size_t)brow * D_;
    for (int i = tid; i < BML * (D_ / 4); i += NTHREADS) {
        int m  = i >> 5;
        int d4 = (i & 31) << 2;
        float4 v = *(const float4*)(Qg + m * D_ + d4);
        __half2 h0 = __floats2half2_rn(v.x, v.y);
        __half2 h1 = __floats2half2_rn(v.z, v.w);
        uint2 u = make_uint2(*(uint32_t*)&h0, *(uint32_t*)&h1);
        *(uint2*)&Qsw[(m * QPH + d4) >> 1] = u;
    }

    const __half* KhB = g_Kh + (size_t)b * NK_ * D_;
    auto stageK = [&](int buf, int kt) {
        uint32_t kdst = sb + LKS_OFF + buf * LKS_BYTES;
        const __half* ksrc = KhB + (size_t)(kt * BN) * D_;
        #pragma unroll
        for (int r = 0; r < 4; r++) {
            int i = tid + r * NTHREADS;          // < 1024
            int row = i >> 4, off = i & 15;
            cp16(kdst + row * (KPH * 2) + off * 16, ksrc + row * D_ + off * 8);
        }
        asm volatile("cp.async.commit_group;");
    };
    stageK(0, 0);
    __syncthreads();                             // Q visible

    const uint32_t qaddr0 = sb + LQS_OFF +
        (uint32_t)((wm * 16 + rr + (mi & 1) * 8) * QPH + (mi >> 1) * 8) * 2;
    uint32_t qf[8][4];
    #pragma unroll
    for (int ks = 0; ks < 8; ++ks) ldsm_x4(qf[ks], qaddr0 + (uint32_t)(ks * 16) * 2);

    const uint32_t koff0 = (uint32_t)(((mi >> 1) * 8 + rr) * KPH + (mi & 1) * 8) * 2;
    float ls0 = 0.0f, ls1 = 0.0f;

    for (int kt = 0; kt < NT; ++kt) {
        const int cur = kt & 1;
        __syncthreads();
        if (kt + 1 < NT) { stageK(cur ^ 1, kt + 1); asm volatile("cp.async.wait_group 1;"); }
        else             { asm volatile("cp.async.wait_group 0;"); }
        __syncthreads();

        const uint32_t kbase = sb + LKS_OFF + cur * LKS_BYTES + koff0;

        float sacc[8][4];
        #pragma unroll
        for (int j = 0; j < 8; j++)
            #pragma unroll
            for (int r = 0; r < 4; r++) sacc[j][r] = 0.0f;

        #pragma unroll
        for (int ks = 0; ks < 8; ++ks) {
            #pragma unroll
            for (int jn = 0; jn < 4; ++jn) {
                uint32_t bb[4];
                ldsm_x4(bb, kbase + (uint32_t)(jn * 16 * KPH + ks * 16) * 2);
                mma_f16(sacc[2*jn][0], sacc[2*jn][1], sacc[2*jn][2], sacc[2*jn][3],
                        qf[ks][0], qf[ks][1], qf[ks][2], qf[ks][3], bb[0], bb[1]);
                mma_f16(sacc[2*jn+1][0], sacc[2*jn+1][1], sacc[2*jn+1][2], sacc[2*jn+1][3],
                        qf[ks][0], qf[ks][1], qf[ks][2], qf[ks][3], bb[2], bb[3]);
            }
        }
        #pragma unroll
        for (int j = 0; j < 8; j++) {
            ls0 += exp2f(sacc[j][0]) + exp2f(sacc[j][1]);
            ls1 += exp2f(sacc[j][2]) + exp2f(sacc[j][3]);
        }
    }

    ls0 += __shfl_xor_sync(0xffffffffu, ls0, 1);
    ls0 += __shfl_xor_sync(0xffffffffu, ls0, 2);
    ls1 += __shfl_xor_sync(0xffffffffu, ls1, 1);
    ls1 += __shfl_xor_sync(0xffffffffu, ls1, 2);
    if (t == 0) {
        g_inv_l[brow + wm * 16 + g]     = 1.0f / ls0;
        g_inv_l[brow + wm * 16 + 8 + g] = 1.0f / ls1;
    }
}

// ---------------------------------------------------------------------------
// Pass 2 (BM=64, 2 CTAs/SM): write NORMALIZED attention directly, compute O.
// Warp = (m16 slab) x (key half): S over its n32, exp'd fragments feed PV's
// k32 chunk directly in registers; O partials reduced through smem once.
// ---------------------------------------------------------------------------
__global__ void __launch_bounds__(NTHREADS, 2)
attn_kernel(const float* __restrict__ Q, float* __restrict__ out,
            float* __restrict__ attn)
{
    uint32_t sb = (uint32_t)__cvta_generic_to_shared(smem);
    uint32_t* Qsw = (uint32_t*)(smem + AQS_OFF);

    const int b    = blockIdx.y;
    const int brow = b * NQ_ + blockIdx.x * BMA;

    const int tid  = threadIdx.x;
    const int lane = tid & 31;
    const int wid  = tid >> 5;
    const int wm   = wid & 3;          // m16 slab
    const int wn   = wid >> 2;         // key half (0/1)
    const int g    = lane >> 2;
    const int t    = lane & 3;
    const int mi   = lane >> 3;
    const int rr   = lane & 7;

    const float inv0 = g_inv_l[brow + wm * 16 + g];
    const float inv1 = g_inv_l[brow + wm * 16 + 8 + g];

    // stage Q fp32 -> fp16 smem
    const float* Qg = Q + (size_t)brow * D_;
    for (int i = tid; i < BMA * (D_ / 4); i += NTHREADS) {
        int m  = i >> 5;
        int d4 = (i & 31) << 2;
        float4 v = *(const float4*)(Qg + m * D_ + d4);
        __half2 h0 = __floats2half2_rn(v.x, v.y);
        __half2 h1 = __floats2half2_rn(v.z, v.w);
        uint2 u = make_uint2(*(uint32_t*)&h0, *(uint32_t*)&h1);
        *(uint2*)&Qsw[(m * QPH + d4) >> 1] = u;
    }

    const __half* KhB = g_Kh + (size_t)b * NK_ * D_;
    const __half* VhB = g_Vh + (size_t)b * NK_ * D_;
    auto stageKV = [&](int buf, int kt) {
        const int k0 = kt * BN;
        uint32_t kdst = sb + AKS_OFF + buf * AKS_BYTES;
        uint32_t vdst = sb + AVS_OFF + buf * AVS_BYTES;
        const __half* ksrc = KhB + (size_t)k0 * D_;
        const __half* vsrc = VhB + (size_t)k0 * D_;
        #pragma unroll
        for (int r = 0; r < 4; r++) {
            int i = tid + r * NTHREADS;          // < 1024
            int row = i >> 4, off = i & 15;
            cp16(kdst + row * (KPH * 2) + off * 16, ksrc + row * D_ + off * 8);
            cp16(vdst + row * (VPH * 2) + off * 16, vsrc + row * D_ + off * 8);
        }
        asm volatile("cp.async.commit_group;");
    };
    stageKV(0, 0);
    __syncthreads();                             // Q visible

    const uint32_t qaddr0 = sb + AQS_OFF +
        (uint32_t)((wm * 16 + rr + (mi & 1) * 8) * QPH + (mi >> 1) * 8) * 2;
    const uint32_t koff0 = (uint32_t)(((wn * 32 + (mi >> 1) * 8 + rr)) * KPH + (mi & 1) * 8) * 2;
    const uint32_t voff0 = (uint32_t)((((mi & 1) * 8 + rr)) * VPH + (mi >> 1) * 8) * 2;

    float oacc[16][4];
    #pragma unroll
    for (int j = 0; j < 16; j++)
        #pragma unroll
        for (int r = 0; r < 4; r++) oacc[j][r] = 0.0f;

    float* arow0 = attn + (size_t)(brow + wm * 16 + g) * NK_;
    float* arow1 = attn + (size_t)(brow + wm * 16 + 8 + g) * NK_;

    for (int kt = 0; kt < NT; ++kt) {
        const int cur = kt & 1;
        const int k0  = kt * BN;

        __syncthreads();
        if (kt + 1 < NT) { stageKV(cur ^ 1, kt + 1); asm volatile("cp.async.wait_group 1;"); }
        else             { asm volatile("cp.async.wait_group 0;"); }
        __syncthreads();

        const uint32_t kbase = sb + AKS_OFF + cur * AKS_BYTES + koff0;
        const uint32_t vbase = sb + AVS_OFF + cur * AVS_BYTES + voff0;

        // ---- S = Q K'^T : m16 x n32 (this warp's key half), k=128 ----
        float sacc[4][4];
        #pragma unroll
        for (int j = 0; j < 4; j++)
            #pragma unroll
            for (int r = 0; r < 4; r++) sacc[j][r] = 0.0f;

        #pragma unroll
        for (int ks = 0; ks < 8; ++ks) {
            uint32_t qf[4];
            ldsm_x4(qf, qaddr0 + (uint32_t)(ks * 16) * 2);
            #pragma unroll
            for (int jn = 0; jn < 2; ++jn) {
                uint32_t bb[4];
                ldsm_x4(bb, kbase + (uint32_t)(jn * 16 * KPH + ks * 16) * 2);
                mma_f16(sacc[2*jn][0], sacc[2*jn][1], sacc[2*jn][2], sacc[2*jn][3],
                        qf[0], qf[1], qf[2], qf[3], bb[0], bb[1]);
                mma_f16(sacc[2*jn+1][0], sacc[2*jn+1][1], sacc[2*jn+1][2], sacc[2*jn+1][3],
                        qf[0], qf[1], qf[2], qf[3], bb[2], bb[3]);
            }
        }

        // ---- epilogue: E = exp2(S); write NORMALIZED attn; build PV A frags ----
        uint32_t ah[4][2];
        #pragma unroll
        for (int j = 0; j < 4; j++) {
            float e0 = exp2f(sacc[j][0]);
            float e1 = exp2f(sacc[j][1]);
            float e2 = exp2f(sacc[j][2]);
            float e3 = exp2f(sacc[j][3]);
            __half2 h0 = __floats2half2_rn(e0, e1);
            __half2 h1 = __floats2half2_rn(e2, e3);
            ah[j][0] = *(uint32_t*)&h0;
            ah[j][1] = *(uint32_t*)&h1;
            const int c = k0 + wn * 32 + j * 8 + 2 * t;
            *(float2*)(arow0 + c) = make_float2(e0 * inv0, e1 * inv0);
            *(float2*)(arow1 + c) = make_float2(e2 * inv1, e3 * inv1);
        }

        // ---- O += E V : m16 x d128 over this warp's k32 (2 k16 chunks) ----
        #pragma unroll
        for (int kc = 0; kc < 2; ++kc) {
            const uint32_t a0 = ah[2*kc][0],   a1 = ah[2*kc][1];
            const uint32_t a2 = ah[2*kc+1][0], a3 = ah[2*kc+1][1];
            const uint32_t vrow = vbase + (uint32_t)((wn * 32 + kc * 16) * VPH) * 2;
            #pragma unroll
            for (int j16 = 0; j16 < 8; ++j16) {
                uint32_t bb[4];
                ldsm_x4_trans(bb, vrow + (uint32_t)(j16 * 16) * 2);
                mma_f16(oacc[2*j16][0], oacc[2*j16][1], oacc[2*j16][2], oacc[2*j16][3],
                        a0, a1, a2, a3, bb[0], bb[1]);
                mma_f16(oacc[2*j16+1][0], oacc[2*j16+1][1], oacc[2*j16+1][2], oacc[2*j16+1][3],
                        a0, a1, a2, a3, bb[2], bb[3]);
            }
        }
    }

    // ---- cross-half O reduction through smem (one time) ----
    float* red = (float*)(smem + AKS_OFF);   // K buffers are dead now
    __syncthreads();                          // everyone done with K/V smem
    if (wn == 1) {
        #pragma unroll
        for (int j = 0; j < 16; j++) {
            *(float2*)&red[(wm * 16 + g) * RP + j * 8 + 2 * t] =
                make_float2(oacc[j][0], oacc[j][1]);
            *(float2*)&red[(wm * 16 + 8 + g) * RP + j * 8 + 2 * t] =
                make_float2(oacc[j][2], oacc[j][3]);
        }
    }
    __syncthreads();
    if (wn == 0) {
        float* orow0 = out + (size_t)(brow + wm * 16 + g) * D_;
        float* orow1 = out + (size_t)(brow + wm * 16 + 8 + g) * D_;
        #pragma unroll
        for (int j = 0; j < 16; j++) {
            float2 p0 = *(float2*)&red[(wm * 16 + g) * RP + j * 8 + 2 * t];
            float2 p1 = *(float2*)&red[(wm * 16 + 8 + g) * RP + j * 8 + 2 * t];
            const int c = j * 8 + 2 * t;
            *(float2*)(orow0 + c) = make_float2((oacc[j][0] + p0.x) * inv0,
                                                (oacc[j][1] + p0.y) * inv0);
            *(float2*)(orow1 + c) = make_float2((oacc[j][2] + p1.x) * inv1,
                                                (oacc[j][3] + p1.y) * inv1);
        }
    }
}

// ---------------------------------------------------------------------------
extern "C" void kernel_launch(void* const* d_in, const int* in_sizes, int n_in,
                              void* d_out, int out_size) {
    const float* Q      = (const float*)d_in[0];
    const float* K      = (const float*)d_in[1];
    const float* V      = (const float*)d_in[2];
    const float* phases = (const float*)d_in[3];

    float* out  = (float*)d_out;
    float* attn = out + (size_t)B_ * NQ_ * D_;   // outputs: (output, attention)

    (void)in_sizes; (void)n_in; (void)out_size;

    cudaFuncSetAttribute(lsum_kernel,
                         cudaFuncAttributeMaxDynamicSharedMemorySize, LSM_BYTES);
    cudaFuncSetAttribute(attn_kernel,
                         cudaFuncAttributeMaxDynamicSharedMemorySize, ASM_BYTES);

    gate_kernel<<<(NK_ + 255) / 256, 256>>>(phases);
    convK_kernel<<<(B_ * NK_ * D_ / 4) / 256, 256>>>(K);
    convV_kernel<<<(B_ * NK_ * D_ / 4) / 256, 256>>>(V);

    dim3 gl(NQ_ / BML, B_);
    lsum_kernel<<<gl, NTHREADS, LSM_BYTES>>>(Q);

    dim3 ga(NQ_ / BMA, B_);
    attn_kernel<<<ga, NTHREADS, ASM_BYTES>>>(Q, out, attn);
}

// round 16
// speedup vs baseline: 1.2625x; 1.2625x over previous
#include <cuda_runtime.h>
#include <cuda_fp16.h>
#include <math.h>
#include <stdint.h>

// Problem constants (fixed by the reference)
#define B_   16
#define NQ_  2048
#define NK_  2048
#define D_   128

#define BM   128     // queries per block (attn + lsum)
#define BN   64      // keys per tile
#define NT   32      // NK_/BN
#define NTHREADS 256 // 8 warps

// smem pitches in halves — word-pitch ≡ 4 (mod 32) -> conflict-free ldmatrix
#define QPH 136
#define KPH 136
#define VPH 136

#define TILE_BYTES (BN * KPH * 2)               // 17408: one K or V tile image

// ---- attn kernel smem layout ----
#define QS_OFF   0
#define QS_BYTES (BM * QPH * 2)                 // 34816
#define KS_OFF   (QS_OFF + QS_BYTES)
#define VS_OFF   (KS_OFF + 2 * TILE_BYTES)
#define AMB_OFF  (VS_OFF + 2 * TILE_BYTES)      // 104448: 2 mbarriers
#define ASM_BYTES (AMB_OFF + 16)                // 104464

// ---- lsum kernel smem layout ----
#define LKS_OFF  (QS_OFF + QS_BYTES)
#define LMB_OFF  (LKS_OFF + 2 * TILE_BYTES)     // 69632
#define LSM_BYTES (LMB_OFF + 16)                // 69648  (x2 CTAs fits)

__device__ float  g_gate[NK_];                  // gate * scale * log2(e)
__device__ float  g_inv_l[B_ * NQ_];
// tile-blocked, pre-swizzled gmem images: [b*NT+kt][BN][KPH] halves
__device__ __align__(128) __half g_Kt[(size_t)B_ * NT * BN * KPH];
__device__ __align__(128) __half g_Vt[(size_t)B_ * NT * BN * KPH];

// ---------------------------------------------------------------------------
__global__ void gate_kernel(const float* __restrict__ phases) {
    int k = blockIdx.x * blockDim.x + threadIdx.x;
    if (k < NK_) {
        const float TWO_PI = 6.283185307179586f;
        const float INV_2PW2 = 1.0f / 1.2337005501361697f; // 2*(2pi/8)^2
        const float SCALE = 0.08838834764831845f;          // 1/sqrt(128)
        const float LOG2E = 1.4426950408889634f;
        float p = fabsf(phases[k]);
        float pd = fminf(p, TWO_PI - p);
        g_gate[k] = expf(-pd * pd * INV_2PW2) * SCALE * LOG2E;
    }
}

// K -> fp16 (gate*scale*log2e folded) into tile-blocked pitched image.
__global__ void convK_kernel(const float* __restrict__ K) {
    int i = blockIdx.x * blockDim.x + threadIdx.x;   // < B*NK*D/4 = 2^20
    int d4  = (i & 31) << 2;
    int row = i >> 5;                                 // global row b*NK+n
    float gs = g_gate[row & (NK_ - 1)];
    float4 v = *(const float4*)(K + (size_t)row * D_ + d4);
    __half2 h0 = __floats2half2_rn(v.x * gs, v.y * gs);
    __half2 h1 = __floats2half2_rn(v.z * gs, v.w * gs);
    uint2 u = make_uint2(*(uint32_t*)&h0, *(uint32_t*)&h1);
    size_t dst = (size_t)(row >> 6) * (BN * KPH) + (row & 63) * KPH + d4;
    *(uint2*)&g_Kt[dst] = u;
}

// V -> fp16 into tile-blocked pitched image.
__global__ void convV_kernel(const float* __restrict__ V) {
    int i = blockIdx.x * blockDim.x + threadIdx.x;   // < 2^20
    int d4  = (i & 31) << 2;
    int row = i >> 5;
    float4 v = *(const float4*)(V + (size_t)row * D_ + d4);
    __half2 h0 = __floats2half2_rn(v.x, v.y);
    __half2 h1 = __floats2half2_rn(v.z, v.w);
    uint2 u = make_uint2(*(uint32_t*)&h0, *(uint32_t*)&h1);
    size_t dst = (size_t)(row >> 6) * (BN * VPH) + (row & 63) * VPH + d4;
    *(uint2*)&g_Vt[dst] = u;
}

// ---------------------------------------------------------------------------
__device__ __forceinline__ void mma_f16(
    float& d0, float& d1, float& d2, float& d3,
    uint32_t a0, uint32_t a1, uint32_t a2, uint32_t a3,
    uint32_t b0, uint32_t b1)
{
    asm volatile(
        "mma.sync.aligned.m16n8k16.row.col.f32.f16.f16.f32 "
        "{%0,%1,%2,%3}, {%4,%5,%6,%7}, {%8,%9}, {%0,%1,%2,%3};"
        : "+f"(d0), "+f"(d1), "+f"(d2), "+f"(d3)
        : "r"(a0), "r"(a1), "r"(a2), "r"(a3), "r"(b0), "r"(b1));
}

__device__ __forceinline__ void ldsm_x4(uint32_t* r, uint32_t addr) {
    asm volatile("ldmatrix.sync.aligned.m8n8.x4.shared.b16 {%0,%1,%2,%3}, [%4];"
                 : "=r"(r[0]), "=r"(r[1]), "=r"(r[2]), "=r"(r[3]) : "r"(addr));
}

__device__ __forceinline__ void ldsm_x4_trans(uint32_t* r, uint32_t addr) {
    asm volatile("ldmatrix.sync.aligned.m8n8.x4.trans.shared.b16 {%0,%1,%2,%3}, [%4];"
                 : "=r"(r[0]), "=r"(r[1]), "=r"(r[2]), "=r"(r[3]) : "r"(addr));
}

__device__ __forceinline__ void mbar_init(uint32_t mbar) {
    asm volatile("mbarrier.init.shared.b64 [%0], 1;" :: "r"(mbar) : "memory");
}

__device__ __forceinline__ void mbar_expect_tx(uint32_t mbar, uint32_t bytes) {
    asm volatile("mbarrier.arrive.expect_tx.shared::cta.b64 _, [%0], %1;"
                 :: "r"(mbar), "r"(bytes) : "memory");
}

__device__ __forceinline__ void mbar_wait(uint32_t mbar, uint32_t parity) {
    asm volatile(
        "{\n\t.reg .pred P;\n"
        "WAIT_%=:\n\t"
        "mbarrier.try_wait.parity.acquire.cta.shared::cta.b64 P, [%0], %1, 0x989680;\n\t"
        "@!P bra WAIT_%=;\n\t}"
        :: "r"(mbar), "r"(parity) : "memory");
}

__device__ __forceinline__ void bulk_g2s(uint32_t dst, const void* src,
                                         uint32_t bytes, uint32_t mbar) {
    asm volatile(
        "cp.async.bulk.shared::cluster.global.mbarrier::complete_tx::bytes "
        "[%0], [%1], %2, [%3];"
        :: "r"(dst), "l"(src), "r"(bytes), "r"(mbar) : "memory");
}

// ---------------------------------------------------------------------------
// Pass 1: l[b,q] = sum_k exp2(q . k'), k' = K*gate*scale*log2e. Writes inv_l.
// 8 warps, warp = m16 slab, full n64 per tile. Q fragments hoisted in regs.
// TMA-bulk double-buffered K tiles.
// ---------------------------------------------------------------------------
extern __shared__ char smem[];

__global__ void __launch_bounds__(NTHREADS, 2)
lsum_kernel(const float* __restrict__ Q)
{
    uint32_t sb = (uint32_t)__cvta_generic_to_shared(smem);
    uint32_t* Qsw = (uint32_t*)(smem + QS_OFF);

    const int b    = blockIdx.y;
    const int brow = b * NQ_ + blockIdx.x * BM;

    const int tid  = threadIdx.x;
    const int lane = tid & 31;
    const int wm   = tid >> 5;         // 0..7 -> m16 slab
    const int g    = lane >> 2;
    const int t    = lane & 3;
    const int mi   = lane >> 3;
    const int rr   = lane & 7;

    // stage Q fp32 -> fp16 smem
    const float* Qg = Q + (size_t)brow * D_;
    for (int i = tid; i < BM * (D_ / 4); i += NTHREADS) {
        int m  = i >> 5;
        int d4 = (i & 31) << 2;
        float4 v = *(const float4*)(Qg + m * D_ + d4);
        __half2 h0 = __floats2half2_rn(v.x, v.y);
        __half2 h1 = __floats2half2_rn(v.z, v.w);
        uint2 u = make_uint2(*(uint32_t*)&h0, *(uint32_t*)&h1);
        *(uint2*)&Qsw[(m * QPH + d4) >> 1] = u;
    }

    const __half* KtB = g_Kt + (size_t)b * NT * (BN * KPH);
    if (tid == 0) { mbar_init(sb + LMB_OFF); mbar_init(sb + LMB_OFF + 8); }
    __syncthreads();                             // mbar init + Q visible

    if (tid == 0) {
        mbar_expect_tx(sb + LMB_OFF, TILE_BYTES);
        bulk_g2s(sb + LKS_OFF, KtB, TILE_BYTES, sb + LMB_OFF);
    }

    // hoist Q fragments: m16 x k128
    const uint32_t qaddr0 = sb + QS_OFF +
        (uint32_t)((wm * 16 + rr + (mi & 1) * 8) * QPH + (mi >> 1) * 8) * 2;
    uint32_t qf[8][4];
    #pragma unroll
    for (int ks = 0; ks < 8; ++ks) ldsm_x4(qf[ks], qaddr0 + (uint32_t)(ks * 16) * 2);

    const uint32_t koff0 = (uint32_t)(((mi >> 1) * 8 + rr) * KPH + (mi & 1) * 8) * 2;
    float ls0 = 0.0f, ls1 = 0.0f;
    int ph0 = 0, ph1 = 0;

    for (int kt = 0; kt < NT; ++kt) {
        const int cur = kt & 1;
        __syncthreads();                 // prev compute done with buf cur^1
        if (tid == 0 && kt + 1 < NT) {
            uint32_t mb = sb + LMB_OFF + (cur ^ 1) * 8;
            mbar_expect_tx(mb, TILE_BYTES);
            bulk_g2s(sb + LKS_OFF + (cur ^ 1) * TILE_BYTES,
                     KtB + (size_t)(kt + 1) * (BN * KPH), TILE_BYTES, mb);
        }
        if (cur) { mbar_wait(sb + LMB_OFF + 8, ph1); ph1 ^= 1; }
        else     { mbar_wait(sb + LMB_OFF,     ph0); ph0 ^= 1; }

        const uint32_t kbase = sb + LKS_OFF + cur * TILE_BYTES + koff0;

        float sacc[8][4];
        #pragma unroll
        for (int j = 0; j < 8; j++)
            #pragma unroll
            for (int r = 0; r < 4; r++) sacc[j][r] = 0.0f;

        #pragma unroll
        for (int ks = 0; ks < 8; ++ks) {
            #pragma unroll
            for (int jn = 0; jn < 4; ++jn) {
                uint32_t bb[4];
                ldsm_x4(bb, kbase + (uint32_t)(jn * 16 * KPH + ks * 16) * 2);
                mma_f16(sacc[2*jn][0], sacc[2*jn][1], sacc[2*jn][2], sacc[2*jn][3],
                        qf[ks][0], qf[ks][1], qf[ks][2], qf[ks][3], bb[0], bb[1]);
                mma_f16(sacc[2*jn+1][0], sacc[2*jn+1][1], sacc[2*jn+1][2], sacc[2*jn+1][3],
                        qf[ks][0], qf[ks][1], qf[ks][2], qf[ks][3], bb[2], bb[3]);
            }
        }
        #pragma unroll
        for (int j = 0; j < 8; j++) {
            ls0 += exp2f(sacc[j][0]) + exp2f(sacc[j][1]);
            ls1 += exp2f(sacc[j][2]) + exp2f(sacc[j][3]);
        }
    }

    ls0 += __shfl_xor_sync(0xffffffffu, ls0, 1);
    ls0 += __shfl_xor_sync(0xffffffffu, ls0, 2);
    ls1 += __shfl_xor_sync(0xffffffffu, ls1, 1);
    ls1 += __shfl_xor_sync(0xffffffffu, ls1, 2);
    if (t == 0) {
        g_inv_l[brow + wm * 16 + g]     = 1.0f / ls0;
        g_inv_l[brow + wm * 16 + 8 + g] = 1.0f / ls1;
    }
}

// ---------------------------------------------------------------------------
// Pass 2: with inv_l known, write NORMALIZED attention directly and compute O.
// FA2 register passing (exp'd S fragments feed PV directly); warp = m16 slab
// x full n64/k64. TMA-bulk double-buffered K/V tiles.
// ---------------------------------------------------------------------------
__global__ void __launch_bounds__(NTHREADS, 1)
attn_kernel(const float* __restrict__ Q, float* __restrict__ out,
            float* __restrict__ attn)
{
    uint32_t sb = (uint32_t)__cvta_generic_to_shared(smem);
    uint32_t* Qsw = (uint32_t*)(smem + QS_OFF);

    const int b    = blockIdx.y;
    const int brow = b * NQ_ + blockIdx.x * BM;

    const int tid  = threadIdx.x;
    const int lane = tid & 31;
    const int wm   = tid >> 5;         // 0..7 -> m16 slab
    const int g    = lane >> 2;
    const int t    = lane & 3;
    const int mi   = lane >> 3;
    const int rr   = lane & 7;

    const float inv0 = g_inv_l[brow + wm * 16 + g];
    const float inv1 = g_inv_l[brow + wm * 16 + 8 + g];

    // stage Q fp32 -> fp16 smem
    const float* Qg = Q + (size_t)brow * D_;
    for (int i = tid; i < BM * (D_ / 4); i += NTHREADS) {
        int m  = i >> 5;
        int d4 = (i & 31) << 2;
        float4 v = *(const float4*)(Qg + m * D_ + d4);
        __half2 h0 = __floats2half2_rn(v.x, v.y);
        __half2 h1 = __floats2half2_rn(v.z, v.w);
        uint2 u = make_uint2(*(uint32_t*)&h0, *(uint32_t*)&h1);
        *(uint2*)&Qsw[(m * QPH + d4) >> 1] = u;
    }

    const __half* KtB = g_Kt + (size_t)b * NT * (BN * KPH);
    const __half* VtB = g_Vt + (size_t)b * NT * (BN * VPH);
    if (tid == 0) { mbar_init(sb + AMB_OFF); mbar_init(sb + AMB_OFF + 8); }
    __syncthreads();                             // mbar init + Q visible

    if (tid == 0) {
        mbar_expect_tx(sb + AMB_OFF, 2 * TILE_BYTES);
        bulk_g2s(sb + KS_OFF, KtB, TILE_BYTES, sb + AMB_OFF);
        bulk_g2s(sb + VS_OFF, VtB, TILE_BYTES, sb + AMB_OFF);
    }

    // hoist Q fragments: m16 x k128
    const uint32_t qaddr0 = sb + QS_OFF +
        (uint32_t)((wm * 16 + rr + (mi & 1) * 8) * QPH + (mi >> 1) * 8) * 2;
    uint32_t qf[8][4];
    #pragma unroll
    for (int ks = 0; ks < 8; ++ks) ldsm_x4(qf[ks], qaddr0 + (uint32_t)(ks * 16) * 2);

    const uint32_t koff0 = (uint32_t)(((mi >> 1) * 8 + rr) * KPH + (mi & 1) * 8) * 2;
    const uint32_t voff0 = (uint32_t)((((mi & 1) * 8 + rr)) * VPH + (mi >> 1) * 8) * 2;

    float oacc[16][4];
    #pragma unroll
    for (int j = 0; j < 16; j++)
        #pragma unroll
        for (int r = 0; r < 4; r++) oacc[j][r] = 0.0f;

    float* arow0 = attn + (size_t)(brow + wm * 16 + g) * NK_;
    float* arow1 = attn + (size_t)(brow + wm * 16 + 8 + g) * NK_;
    int ph0 = 0, ph1 = 0;

    for (int kt = 0; kt < NT; ++kt) {
        const int cur = kt & 1;
        const int k0  = kt * BN;

        __syncthreads();                 // all warps done with buf cur^1
        if (tid == 0 && kt + 1 < NT) {
            uint32_t mb = sb + AMB_OFF + (cur ^ 1) * 8;
            mbar_expect_tx(mb, 2 * TILE_BYTES);
            bulk_g2s(sb + KS_OFF + (cur ^ 1) * TILE_BYTES,
                     KtB + (size_t)(kt + 1) * (BN * KPH), TILE_BYTES, mb);
            bulk_g2s(sb + VS_OFF + (cur ^ 1) * TILE_BYTES,
                     VtB + (size_t)(kt + 1) * (BN * VPH), TILE_BYTES, mb);
        }
        if (cur) { mbar_wait(sb + AMB_OFF + 8, ph1); ph1 ^= 1; }
        else     { mbar_wait(sb + AMB_OFF,     ph0); ph0 ^= 1; }

        const uint32_t kbase = sb + KS_OFF + cur * TILE_BYTES + koff0;
        const uint32_t vbase = sb + VS_OFF + cur * TILE_BYTES + voff0;

        // ---- S = Q K'^T : m16 x n64, k=128 ----
        float sacc[8][4];
        #pragma unroll
        for (int j = 0; j < 8; j++)
            #pragma unroll
            for (int r = 0; r < 4; r++) sacc[j][r] = 0.0f;

        #pragma unroll
        for (int ks = 0; ks < 8; ++ks) {
            #pragma unroll
            for (int jn = 0; jn < 4; ++jn) {
                uint32_t bb[4];
                ldsm_x4(bb, kbase + (uint32_t)(jn * 16 * KPH + ks * 16) * 2);
                mma_f16(sacc[2*jn][0], sacc[2*jn][1], sacc[2*jn][2], sacc[2*jn][3],
                        qf[ks][0], qf[ks][1], qf[ks][2], qf[ks][3], bb[0], bb[1]);
                mma_f16(sacc[2*jn+1][0], sacc[2*jn+1][1], sacc[2*jn+1][2], sacc[2*jn+1][3],
                        qf[ks][0], qf[ks][1], qf[ks][2], qf[ks][3], bb[2], bb[3]);
            }
        }

        // ---- epilogue: E = exp2(S); write NORMALIZED attn; build PV A frags ----
        uint32_t ah[8][2];
        #pragma unroll
        for (int j = 0; j < 8; j++) {
            float e0 = exp2f(sacc[j][0]);
            float e1 = exp2f(sacc[j][1]);
            float e2 = exp2f(sacc[j][2]);
            float e3 = exp2f(sacc[j][3]);
            __half2 h0 = __floats2half2_rn(e0, e1);
            __half2 h1 = __floats2half2_rn(e2, e3);
            ah[j][0] = *(uint32_t*)&h0;
            ah[j][1] = *(uint32_t*)&h1;
            const int c = k0 + j * 8 + 2 * t;
            *(float2*)(arow0 + c) = make_float2(e0 * inv0, e1 * inv0);
            *(float2*)(arow1 + c) = make_float2(e2 * inv1, e3 * inv1);
        }

        // ---- O += E V : m16 x d128, k=64 (A from registers, B via ldsm.trans) ----
        #pragma unroll
        for (int ks = 0; ks < 4; ++ks) {
            const uint32_t a0 = ah[2*ks][0],   a1 = ah[2*ks][1];
            const uint32_t a2 = ah[2*ks+1][0], a3 = ah[2*ks+1][1];
            #pragma unroll
            for (int j16 = 0; j16 < 8; ++j16) {
                uint32_t bb[4];
                ldsm_x4_trans(bb, vbase + (uint32_t)(ks * 16 * VPH + j16 * 16) * 2);
                mma_f16(oacc[2*j16][0], oacc[2*j16][1], oacc[2*j16][2], oacc[2*j16][3],
                        a0, a1, a2, a3, bb[0], bb[1]);
                mma_f16(oacc[2*j16+1][0], oacc[2*j16+1][1], oacc[2*j16+1][2], oacc[2*j16+1][3],
                        a0, a1, a2, a3, bb[2], bb[3]);
            }
        }
    }

    // ---- write normalized O ----
    float* orow0 = out + (size_t)(brow + wm * 16 + g) * D_;
    float* orow1 = out + (size_t)(brow + wm * 16 + 8 + g) * D_;
    #pragma unroll
    for (int j = 0; j < 16; j++) {
        const int c = j * 8 + 2 * t;
        *(float2*)(orow0 + c) = make_float2(oacc[j][0] * inv0, oacc[j][1] * inv0);
        *(float2*)(orow1 + c) = make_float2(oacc[j][2] * inv1, oacc[j][3] * inv1);
    }
}

// ---------------------------------------------------------------------------
extern "C" void kernel_launch(void* const* d_in, const int* in_sizes, int n_in,
                              void* d_out, int out_size) {
    const float* Q      = (const float*)d_in[0];
    const float* K      = (const float*)d_in[1];
    const float* V      = (const float*)d_in[2];
    const float* phases = (const float*)d_in[3];

    float* out  = (float*)d_out;
    float* attn = out + (size_t)B_ * NQ_ * D_;   // outputs: (output, attention)

    (void)in_sizes; (void)n_in; (void)out_size;

    cudaFuncSetAttribute(lsum_kernel,
                         cudaFuncAttributeMaxDynamicSharedMemorySize, LSM_BYTES);
    cudaFuncSetAttribute(attn_kernel,
                         cudaFuncAttributeMaxDynamicSharedMemorySize, ASM_BYTES);

    gate_kernel<<<(NK_ + 255) / 256, 256>>>(phases);
    convK_kernel<<<(B_ * NK_ * D_ / 4) / 256, 256>>>(K);
    convV_kernel<<<(B_ * NK_ * D_ / 4) / 256, 256>>>(V);

    dim3 grid(NQ_ / BM, B_);
    lsum_kernel<<<grid, NTHREADS, LSM_BYTES>>>(Q);
    attn_kernel<<<grid, NTHREADS, ASM_BYTES>>>(Q, out, attn);
}